// round 3
// baseline (speedup 1.0000x reference)
#include <cuda_runtime.h>
#include <cuda_bf16.h>
#include <cstdint>
#include <math.h>

// ============================================================================
// InfoNCE loss, GB300 (sm_103a, PTX target sm_103 -> mma.sync HMMA/QMMA path)
//  loss = -log(P / (P + N))
//  P = sum(exp(zi.ziT / T)) : 64 diagonal tiles in bf16 (precision-critical,
//      diag terms exp(10) dominate P), 2016 upper tiles in fp8 weighted x2.
//  N = sum(exp(zi.zjT / T)) : 4096 tiles in fp8.
// ============================================================================

#define N_ROWS   8192
#define DDIM     512
#define BM       128
#define BN       128
#define NTHREADS 256

#define ROW_TILES   64
#define NEG_TILES   (ROW_TILES * ROW_TILES)              // 4096 (fp8, -> N)
#define UPPER_TILES (ROW_TILES * (ROW_TILES - 1) / 2)    // 2016 (fp8, w=2 -> P)
#define DIAG_START  (NEG_TILES + UPPER_TILES)            // 6112
#define TOTAL_TILES (DIAG_START + ROW_TILES)             // 6176

// exp(x/T) = ex2(x * (1/T) * log2(e)), T = 0.1
#define EXP_SCALE 14.4269504088896340736f

__device__ __nv_bfloat16 g_zi[(size_t)N_ROWS * DDIM];   // bf16 zi (diag tiles)
__device__ uint8_t       g_fi[(size_t)N_ROWS * DDIM];   // e4m3 zi
__device__ uint8_t       g_fj[(size_t)N_ROWS * DDIM];   // e4m3 zj
__device__ double g_partials[TOTAL_TILES];

// ---------------------------------------------------------------------------
__device__ __forceinline__ uint32_t smem_u32(const void* p) {
    uint32_t a;
    asm("{ .reg .u64 t; cvta.to.shared.u64 t, %1; cvt.u32.u64 %0, t; }" : "=r"(a) : "l"(p));
    return a;
}

#define CP_ASYNC16(dst_u32, src_ptr) \
    asm volatile("cp.async.cg.shared.global [%0], [%1], 16;" \
                 :: "r"(dst_u32), "l"(src_ptr) : "memory")
#define CP_COMMIT() asm volatile("cp.async.commit_group;" ::: "memory")
#define CP_WAIT(n)  asm volatile("cp.async.wait_group %0;" :: "n"(n) : "memory")

__device__ __forceinline__ void ldmx4(uint32_t* r, uint32_t addr) {
    asm volatile("ldmatrix.sync.aligned.m8n8.x4.shared.b16 {%0,%1,%2,%3}, [%4];"
                 : "=r"(r[0]), "=r"(r[1]), "=r"(r[2]), "=r"(r[3]) : "r"(addr));
}

__device__ __forceinline__ void mma_bf16(float* d, const uint32_t* a,
                                         const uint32_t* b) {
    asm volatile(
        "mma.sync.aligned.m16n8k16.row.col.f32.bf16.bf16.f32 "
        "{%0,%1,%2,%3}, {%4,%5,%6,%7}, {%8,%9}, {%0,%1,%2,%3};"
        : "+f"(d[0]), "+f"(d[1]), "+f"(d[2]), "+f"(d[3])
        : "r"(a[0]), "r"(a[1]), "r"(a[2]), "r"(a[3]), "r"(b[0]), "r"(b[1]));
}

__device__ __forceinline__ void mma_fp8(float* d, const uint32_t* a,
                                        const uint32_t* b) {
    asm volatile(
        "mma.sync.aligned.m16n8k32.row.col.f32.e4m3.e4m3.f32 "
        "{%0,%1,%2,%3}, {%4,%5,%6,%7}, {%8,%9}, {%0,%1,%2,%3};"
        : "+f"(d[0]), "+f"(d[1]), "+f"(d[2]), "+f"(d[3])
        : "r"(a[0]), "r"(a[1]), "r"(a[2]), "r"(a[3]), "r"(b[0]), "r"(b[1]));
}

// smem: two buffers of (A 16KB + B 16KB); rows of 128B, swizzle colb^((r&7)<<4)
#define SMEM_BUF_STRIDE 32768
#define SMEM_B_OFF      16384
#define SMEM_DYN_TOTAL  (2 * SMEM_BUF_STRIDE)   // 65536

// ---------------------------------------------------------------------------
// 1) normalize; write e4m3 copies of zi and zj; bf16 copy of zi only.
//    One warp per row; 8 rows per 256-thread block.
// ---------------------------------------------------------------------------
__global__ void __launch_bounds__(256) norm_kernel(const float* __restrict__ zi,
                                                   const float* __restrict__ zj) {
    int row  = blockIdx.x * 8 + (threadIdx.x >> 5);
    int lane = threadIdx.x & 31;
    bool is_i = row < N_ROWS;
    const float* src = is_i ? (zi + (size_t)row * DDIM)
                            : (zj + (size_t)(row - N_ROWS) * DDIM);
    float4 v[4];
    float ss = 0.0f;
    #pragma unroll
    for (int j = 0; j < 4; j++) {
        v[j] = ((const float4*)src)[lane + 32 * j];
        ss += v[j].x * v[j].x + v[j].y * v[j].y + v[j].z * v[j].z + v[j].w * v[j].w;
    }
    #pragma unroll
    for (int o = 16; o; o >>= 1) ss += __shfl_xor_sync(0xFFFFFFFFu, ss, o);
    float inv = 1.0f / fmaxf(sqrtf(ss), 1e-12f);

    // bf16 copy (zi only)
    if (is_i) {
        __nv_bfloat16* dst = g_zi + (size_t)row * DDIM;
        #pragma unroll
        for (int j = 0; j < 4; j++) {
            __nv_bfloat162 p0 = __floats2bfloat162_rn(v[j].x * inv, v[j].y * inv);
            __nv_bfloat162 p1 = __floats2bfloat162_rn(v[j].z * inv, v[j].w * inv);
            uint2 pack;
            pack.x = *reinterpret_cast<uint32_t*>(&p0);
            pack.y = *reinterpret_cast<uint32_t*>(&p1);
            ((uint2*)dst)[lane + 32 * j] = pack;
        }
    }
    // e4m3 copy (both): 16 floats -> 16 bytes per thread, coalesced uint4
    uint8_t* dstf = (is_i ? g_fi : g_fj) +
                    (size_t)(is_i ? row : row - N_ROWS) * DDIM;
    uint4 out;
    uint32_t* ow = reinterpret_cast<uint32_t*>(&out);
    #pragma unroll
    for (int j = 0; j < 4; j++) {
        uint16_t p01, p23;
        asm("cvt.rn.satfinite.e4m3x2.f32 %0, %1, %2;"
            : "=h"(p01) : "f"(v[j].y * inv), "f"(v[j].x * inv));
        asm("cvt.rn.satfinite.e4m3x2.f32 %0, %1, %2;"
            : "=h"(p23) : "f"(v[j].w * inv), "f"(v[j].z * inv));
        ow[j] = (uint32_t)p01 | ((uint32_t)p23 << 16);
    }
    ((uint4*)dstf)[lane] = out;
}

// ---------------------------------------------------------------------------
// 2) fused GEMM + exp-sum.  8 warps = 4(M) x 2(N); warp tile 32x64.
//    Both paths stage 128-byte rows; fp8 k32 step == bf16 k16 step == 32B,
//    so ldmatrix addressing is identical. F8: 4 chunks; bf16: 8 chunks.
// ---------------------------------------------------------------------------
template<bool F8>
__device__ __forceinline__ void run_tile(const char* __restrict__ Ag,
                                         const char* __restrict__ Bg,
                                         char* smem, float acc[2][8][4]) {
    const int RS   = F8 ? (DDIM * 1) : (DDIM * 2);  // row stride bytes
    const int NCH  = F8 ? 4 : 8;                    // 128B K-chunks
    uint32_t sb = smem_u32(smem);
    int tid  = threadIdx.x;
    int lane = tid & 31;
    int wid  = tid >> 5;
    int warp_m = wid & 3;
    int warp_n = wid >> 2;

    int a_row0 = warp_m * 32 + (lane & 15);
    int a_row1 = a_row0 + 16;
    uint32_t a_rb0 = a_row0 * 128, a_xm0 = (a_row0 & 7) << 4;
    uint32_t a_rb1 = a_row1 * 128, a_xm1 = (a_row1 & 7) << 4;
    uint32_t a_csub = (lane >> 4) << 4;

    uint32_t b_rb[4], b_xm[4];
    #pragma unroll
    for (int ntp = 0; ntp < 4; ntp++) {
        int rb = warp_n * 64 + ntp * 16 + ((lane >> 4) << 3) + (lane & 7);
        b_rb[ntp] = rb * 128;
        b_xm[ntp] = (rb & 7) << 4;
    }
    uint32_t b_csub = ((lane >> 3) & 1) << 4;

    #define STAGE_T(buf, kc) do {                                               \
        uint32_t abase = sb + (buf) * SMEM_BUF_STRIDE;                          \
        uint32_t bbase = abase + SMEM_B_OFF;                                    \
        const char* agp = Ag + (size_t)(kc) * 128;                              \
        const char* bgp = Bg + (size_t)(kc) * 128;                              \
        _Pragma("unroll")                                                       \
        for (int j = 0; j < 4; j++) {                                           \
            int i = tid + j * NTHREADS;                                         \
            int r = i >> 3, s = i & 7;                                          \
            uint32_t dst = abase + r * 128 + ((s * 16) ^ ((r & 7) << 4));       \
            CP_ASYNC16(dst, agp + (size_t)r * RS + s * 16);                     \
        }                                                                       \
        _Pragma("unroll")                                                       \
        for (int j = 0; j < 4; j++) {                                           \
            int i = tid + j * NTHREADS;                                         \
            int r = i >> 3, s = i & 7;                                          \
            uint32_t dst = bbase + r * 128 + ((s * 16) ^ ((r & 7) << 4));       \
            CP_ASYNC16(dst, bgp + (size_t)r * RS + s * 16);                     \
        }                                                                       \
    } while (0)

    STAGE_T(0, 0);
    CP_COMMIT();

    for (int kc = 0; kc < NCH; kc++) {
        int cur = kc & 1;
        if (kc + 1 < NCH) {
            STAGE_T(1 - cur, kc + 1);
            CP_COMMIT();
            CP_WAIT(1);
        } else {
            CP_WAIT(0);
        }
        __syncthreads();

        uint32_t abase = sb + cur * SMEM_BUF_STRIDE;
        uint32_t bbase = abase + SMEM_B_OFF;

        #pragma unroll
        for (int kk = 0; kk < 4; kk++) {
            uint32_t kb = kk * 32;
            uint32_t afr[2][4];
            ldmx4(afr[0], abase + a_rb0 + ((kb + a_csub) ^ a_xm0));
            ldmx4(afr[1], abase + a_rb1 + ((kb + a_csub) ^ a_xm1));
            uint32_t bfr[8][2];
            #pragma unroll
            for (int ntp = 0; ntp < 4; ntp++) {
                uint32_t r[4];
                ldmx4(r, bbase + b_rb[ntp] + ((kb + b_csub) ^ b_xm[ntp]));
                bfr[2 * ntp][0] = r[0];     bfr[2 * ntp][1] = r[1];
                bfr[2 * ntp + 1][0] = r[2]; bfr[2 * ntp + 1][1] = r[3];
            }
            #pragma unroll
            for (int mt = 0; mt < 2; mt++)
                #pragma unroll
                for (int nt = 0; nt < 8; nt++) {
                    if (F8) mma_fp8(acc[mt][nt], afr[mt], bfr[nt]);
                    else    mma_bf16(acc[mt][nt], afr[mt], bfr[nt]);
                }
        }
        __syncthreads();
    }
    #undef STAGE_T
}

__global__ void __launch_bounds__(NTHREADS, 2) gemm_kernel() {
    extern __shared__ char smem[];
    int tid  = threadIdx.x;
    int lane = tid & 31;
    int wid  = tid >> 5;

    int b = blockIdx.x;
    int rt, ct, weight;
    bool diag;
    const char* Bmat;
    if (b < NEG_TILES) {
        rt = b >> 6; ct = b & 63; weight = 1; diag = false;
        Bmat = (const char*)g_fj;
    } else if (b < DIAG_START) {
        int k = b - NEG_TILES;
        int r = 0, rowlen = ROW_TILES - 1;
        while (k >= rowlen) { k -= rowlen; rowlen--; r++; }
        rt = r; ct = r + 1 + k; weight = 2; diag = false;
        Bmat = (const char*)g_fi;
    } else {
        rt = ct = b - DIAG_START; weight = 1; diag = true;
        Bmat = (const char*)g_zi;
    }

    float acc[2][8][4];
    #pragma unroll
    for (int mt = 0; mt < 2; mt++)
        #pragma unroll
        for (int nt = 0; nt < 8; nt++)
            #pragma unroll
            for (int i = 0; i < 4; i++) acc[mt][nt][i] = 0.0f;

    if (diag) {
        run_tile<false>((const char*)g_zi + (size_t)rt * BM * DDIM * 2,
                        Bmat + (size_t)ct * BN * DDIM * 2, smem, acc);
    } else {
        run_tile<true>((const char*)g_fi + (size_t)rt * BM * DDIM,
                       Bmat + (size_t)ct * BN * DDIM, smem, acc);
    }

    // epilogue: exp-sum
    float psum = 0.0f;
    #pragma unroll
    for (int mt = 0; mt < 2; mt++)
        #pragma unroll
        for (int nt = 0; nt < 8; nt++)
            #pragma unroll
            for (int i = 0; i < 4; i++) {
                float s = acc[mt][nt][i] * EXP_SCALE;
                float e;
                asm("ex2.approx.ftz.f32 %0, %1;" : "=f"(e) : "f"(s));
                psum += e;
            }
    #pragma unroll
    for (int o = 16; o; o >>= 1) psum += __shfl_xor_sync(0xFFFFFFFFu, psum, o);

    __shared__ float red[8];
    if (lane == 0) red[wid] = psum;
    __syncthreads();
    if (tid == 0) {
        double tot = 0.0;
        #pragma unroll
        for (int w = 0; w < 8; w++) tot += (double)red[w];
        g_partials[blockIdx.x] = tot * (double)weight;
    }
}

// ---------------------------------------------------------------------------
// 3) final reduction -> loss scalar
// ---------------------------------------------------------------------------
__global__ void __launch_bounds__(256) finish_kernel(float* __restrict__ out) {
    int t = threadIdx.x;
    double p = 0.0, n = 0.0;
    for (int i = t; i < TOTAL_TILES; i += 256) {
        double v = g_partials[i];
        if (i < NEG_TILES) n += v; else p += v;
    }
    __shared__ double sp[256], sn[256];
    sp[t] = p; sn[t] = n;
    __syncthreads();
    for (int s = 128; s; s >>= 1) {
        if (t < s) { sp[t] += sp[t + s]; sn[t] += sn[t + s]; }
        __syncthreads();
    }
    if (t == 0) {
        double P = sp[0], N = sn[0];
        out[0] = (float)(-log(P / (N + P)));
    }
}

// ---------------------------------------------------------------------------
extern "C" void kernel_launch(void* const* d_in, const int* in_sizes, int n_in,
                              void* d_out, int out_size) {
    const float* zi = (const float*)d_in[0];
    const float* zj = (const float*)d_in[1];

    cudaFuncSetAttribute(gemm_kernel, cudaFuncAttributeMaxDynamicSharedMemorySize,
                         SMEM_DYN_TOTAL);

    norm_kernel<<<2 * N_ROWS / 8, 256>>>(zi, zj);
    gemm_kernel<<<TOTAL_TILES, NTHREADS, SMEM_DYN_TOTAL>>>();
    finish_kernel<<<1, 256>>>((float*)d_out);
}